// round 8
// baseline (speedup 1.0000x reference)
#include <cuda_runtime.h>
#include <cuda_fp16.h>
#include <cstdint>
#include <math.h>

#define T_STEPS 512
#define BATCH   64
#define IN_DIM  1024
#define HID     1024
#define GATES   4096
#define NCTA    128

// ---------------- static scratch ----------------
__device__ uint32_t g_xfrag[(size_t)T_STEPS * 32768];   // 64 MB: x fp16, mma A-frag layout
__device__ uint32_t g_hfrag[(size_t)T_STEPS * 32768];   // 64 MB: h fp16, mma A-frag layout
__device__ int      g_flags[T_STEPS];

// ---------------- helpers ----------------
__device__ __forceinline__ uint32_t pack2h(__half a, __half b) {
    __half2 t = __halves2half2(a, b);
    return *reinterpret_cast<uint32_t*>(&t);
}
__device__ __forceinline__ void mma16816h(float* c, const uint32_t* a, const uint32_t* b) {
    asm volatile(
        "mma.sync.aligned.m16n8k16.row.col.f32.f16.f16.f32 "
        "{%0,%1,%2,%3}, {%4,%5,%6,%7}, {%8,%9}, {%0,%1,%2,%3};\n"
        : "+f"(c[0]), "+f"(c[1]), "+f"(c[2]), "+f"(c[3])
        : "r"(a[0]), "r"(a[1]), "r"(a[2]), "r"(a[3]), "r"(b[0]), "r"(b[1]));
}
__device__ __forceinline__ void flag_release_add(int* p) {
    asm volatile("red.release.gpu.global.add.s32 [%0], %1;" :: "l"(p), "r"(1) : "memory");
}
__device__ __forceinline__ int flag_acquire_ld(const int* p) {
    int v;
    asm volatile("ld.acquire.gpu.global.s32 %0, [%1];" : "=r"(v) : "l"(p) : "memory");
    return v;
}

// =====================================================================
// Converter: x fp32 -> fp16 mma A-fragment layout.
// frag addr (u32): t*32768 + kt*512 + mt*128 + fl*4 + rg
//   fl(lane) = (r&7)*4 + ((kk>>1)&3), rg = ((kk>>3)<<1) | (r>>3)
//   r = row within 16-row m-tile, kk = k within 16-k tile, pairs (k, k+1) per u32.
// grid (64 kt, 512 t), block 128 (warp = mt, lane = fl); uint4 store = coalesced.
// =====================================================================
__global__ __launch_bounds__(128)
void convert_x_kernel(const float* __restrict__ X)
{
    if (blockIdx.x == 0 && blockIdx.y == 0) {
        #pragma unroll
        for (int i = 0; i < 4; i++) g_flags[threadIdx.x + 128 * i] = 0;
    }
    const int kt = blockIdx.x;
    const int t  = blockIdx.y;
    const int mt = threadIdx.x >> 5;
    const int fl = threadIdx.x & 31;
    const int g  = fl >> 2;
    const int tg = fl & 3;
    const int bb = mt * 16 + g;
    const int k  = kt * 16 + tg * 2;

    const float* xt = X + (size_t)t * BATCH * IN_DIM;
    float2 r00 = *(const float2*)(xt + (size_t)bb * IN_DIM + k);
    float2 r10 = *(const float2*)(xt + (size_t)(bb + 8) * IN_DIM + k);
    float2 r01 = *(const float2*)(xt + (size_t)bb * IN_DIM + k + 8);
    float2 r11 = *(const float2*)(xt + (size_t)(bb + 8) * IN_DIM + k + 8);
    uint4 o;
    o.x = pack2h(__float2half(r00.x), __float2half(r00.y));
    o.y = pack2h(__float2half(r10.x), __float2half(r10.y));
    o.z = pack2h(__float2half(r01.x), __float2half(r01.y));
    o.w = pack2h(__float2half(r11.x), __float2half(r11.y));
    *(uint4*)(g_xfrag + (size_t)t * 32768 + kt * 512 + mt * 128 + fl * 4) = o;
}

// =====================================================================
// Fused persistent LSTM kernel. CTA owns 8 hidden cols (32 gate cols).
// Per step: acc = x_t @ Wx_slice  (no dependency -> before the spin)
//           acc += h(t-1) @ Wh_slice (after flag)
// Warp = (mt = w&3: 16 batch rows, kh = w>>2: k-half). Partial sums meet
// in gbuf; activations in fp32; h published as fp16 A-fragments.
// =====================================================================
#define WS_PITCH 520      // u32 per W column (520 % 32 == 8 -> conflict-free)

__global__ __launch_bounds__(256, 1)
void lstm_fused_kernel(const float* __restrict__ Wx,
                       const float* __restrict__ Wh,
                       const float* __restrict__ b,
                       float* __restrict__ out,
                       int write_tail)
{
    extern __shared__ char smraw[];
    uint32_t* Wxs = (uint32_t*)smraw;                  // 32*520 u32 = 66560 B
    uint32_t* Whs = Wxs + 32 * WS_PITCH;               // 66560 B
    float*    gb  = (float*)(Whs + 32 * WS_PITCH);     // 2 * [64][33] = 16896 B

    const int tid  = threadIdx.x;
    const int lane = tid & 31;
    const int warp = tid >> 5;
    const int g    = lane >> 2;
    const int tg   = lane & 3;
    const int mt   = warp & 3;        // m-tile (16 batch rows)
    const int kh   = warp >> 2;       // k-half
    const int wm   = mt * 16;
    const int j0   = blockIdx.x * 8;

    // ---- one-time: Wx & Wh slices -> SMEM fragment layout (fp16) ----
    for (int i = tid; i < 32 * 1024; i += 256) {
        int c = i & 31;
        int k = i >> 5;
        int col = (c >> 3) * HID + j0 + (c & 7);
        int kt = k >> 4, t4 = (k >> 1) & 3, w = (k >> 3) & 1, hf = k & 1;
        int word = c * WS_PITCH + kt * 8 + t4 * 2 + w;
        ((__half*)Wxs)[word * 2 + hf] = __float2half(Wx[(size_t)k * GATES + col]);
        ((__half*)Whs)[word * 2 + hf] = __float2half(Wh[(size_t)k * GATES + col]);
    }
    __syncthreads();

    // ---- per-thread bias for the activation stage ----
    float breg[2][4];
    #pragma unroll
    for (int rr = 0; rr < 2; rr++) {
        int p = tid + 256 * rr;
        int jg = j0 + (p & 7);
        breg[rr][0] = b[jg];
        breg[rr][1] = b[HID + jg];
        breg[rr][2] = b[2 * HID + jg];
        breg[rr][3] = b[3 * HID + jg];
    }

    float creg[2] = {0.f, 0.f};

    for (int t = 0; t < T_STEPS; t++) {
        float acc[4][4];
        #pragma unroll
        for (int n2 = 0; n2 < 4; n2++)
            #pragma unroll
            for (int c2 = 0; c2 < 4; c2++) acc[n2][c2] = 0.f;

        // ============ x-part: no dependency, runs during the wait window ====
        {
            const uint32_t* ab = g_xfrag + (size_t)t * 32768
                                 + (size_t)kh * 16384 + mt * 128 + lane * 4;
            uint4 H[4];
            #pragma unroll
            for (int q = 0; q < 4; q++) H[q] = *(const uint4*)(ab + q * 512);
            #pragma unroll 4
            for (int kt2 = 0; kt2 < 32; kt2++) {
                int s = kt2 & 3;
                uint32_t ah[4] = {H[s].x, H[s].y, H[s].z, H[s].w};
                int ktg = kh * 32 + kt2;
                #pragma unroll
                for (int nt = 0; nt < 4; nt++) {
                    int c = nt * 8 + g;
                    uint2 bf = *(const uint2*)(Wxs + c * WS_PITCH + ktg * 8 + tg * 2);
                    uint32_t bh[2] = {bf.x, bf.y};
                    mma16816h(acc[nt], ah, bh);
                }
                if (kt2 + 4 < 32) H[s] = *(const uint4*)(ab + (kt2 + 4) * 512);
            }
        }

        // ============ h-part: gated on h(t-1) publication =================
        if (t > 0) {
            if (tid == 0) {
                while (flag_acquire_ld(g_flags + (t - 1)) != NCTA) { }
            }
            __syncthreads();

            const uint32_t* ab = g_hfrag + (size_t)(t - 1) * 32768
                                 + (size_t)kh * 16384 + mt * 128 + lane * 4;
            uint4 H[4];
            #pragma unroll
            for (int q = 0; q < 4; q++) H[q] = *(const uint4*)(ab + q * 512);
            #pragma unroll 4
            for (int kt2 = 0; kt2 < 32; kt2++) {
                int s = kt2 & 3;
                uint32_t ah[4] = {H[s].x, H[s].y, H[s].z, H[s].w};
                int ktg = kh * 32 + kt2;
                #pragma unroll
                for (int nt = 0; nt < 4; nt++) {
                    int c = nt * 8 + g;
                    uint2 bf = *(const uint2*)(Whs + c * WS_PITCH + ktg * 8 + tg * 2);
                    uint32_t bh[2] = {bf.x, bf.y};
                    mma16816h(acc[nt], ah, bh);
                }
                if (kt2 + 4 < 32) H[s] = *(const uint4*)(ab + (kt2 + 4) * 512);
            }
        }

        // ---- partial gate sums -> gbuf half kh ----
        {
            float* gbk = gb + kh * 2112;
            #pragma unroll
            for (int nt = 0; nt < 4; nt++) {
                int r = wm + g;
                int c = nt * 8 + 2 * tg;
                gbk[r * 33 + c]           = acc[nt][0];
                gbk[r * 33 + c + 1]       = acc[nt][1];
                gbk[(r + 8) * 33 + c]     = acc[nt][2];
                gbk[(r + 8) * 33 + c + 1] = acc[nt][3];
            }
        }
        __syncthreads();

        // ---- activations + fragment publish ----
        float hnv[2], cnv[2];
        #pragma unroll
        for (int rr = 0; rr < 2; rr++) {
            int p  = tid + 256 * rr;
            int bb = p >> 3, j = p & 7;
            int jg = j0 + j;
            float gi = gb[bb * 33 +  0 + j] + gb[2112 + bb * 33 +  0 + j] + breg[rr][0];
            float gf = gb[bb * 33 +  8 + j] + gb[2112 + bb * 33 +  8 + j] + breg[rr][1];
            float gg = gb[bb * 33 + 16 + j] + gb[2112 + bb * 33 + 16 + j] + breg[rr][2];
            float go = gb[bb * 33 + 24 + j] + gb[2112 + bb * 33 + 24 + j] + breg[rr][3];
            float iv = 1.f / (1.f + expf(-gi));
            float fv = 1.f / (1.f + expf(-gf));
            float gv = tanhf(gg);
            float ov = 1.f / (1.f + expf(-go));
            float cn = fv * creg[rr] + iv * gv;
            float hn = ov * tanhf(cn);
            creg[rr] = cn;
            hnv[rr] = hn; cnv[rr] = cn;

            // publish h (fp16) in A-fragment layout
            uint32_t mypk = (uint32_t)__half_as_ushort(__float2half(hn));
            uint32_t pp   = __shfl_xor_sync(0xffffffffu, mypk, 1);
            if ((tid & 1) == 0) {
                uint32_t pair = mypk | (pp << 16);
                int kt = jg >> 4, kk = jg & 15, mtt = bb >> 4, r = bb & 15;
                int fl = (r & 7) * 4 + ((kk >> 1) & 3);
                int rg = ((kk >> 3) << 1) | (r >> 3);
                size_t fb = (size_t)t * 32768 + kt * 512 + mtt * 128 + fl * 4 + rg;
                g_hfrag[fb] = pair;
            }
        }

        __syncthreads();
        if (tid == 0) flag_release_add(g_flags + t);

        // ---- off-critical-path output stores ----
        float* hdst = out + (size_t)t * BATCH * HID;
        #pragma unroll
        for (int rr = 0; rr < 2; rr++) {
            int p  = tid + 256 * rr;
            int bb = p >> 3, j = p & 7;
            int jg = j0 + j;
            hdst[(size_t)bb * HID + jg] = hnv[rr];
            if (t == T_STEPS - 1 && write_tail) {
                size_t base = (size_t)T_STEPS * BATCH * HID;
                out[base + (size_t)bb * HID + jg] = hnv[rr];
                out[base + BATCH * HID + (size_t)bb * HID + jg] = cnv[rr];
            }
        }
    }
}

// =====================================================================
extern "C" void kernel_launch(void* const* d_in, const int* in_sizes, int n_in,
                              void* d_out, int out_size)
{
    const float* x  = (const float*)d_in[0];   // [512,64,1024]
    const float* Wx = (const float*)d_in[1];   // [1024,4096]
    const float* Wh = (const float*)d_in[2];   // [1024,4096]
    const float* b  = (const float*)d_in[3];   // [4096]
    float* out = (float*)d_out;

    convert_x_kernel<<<dim3(64, T_STEPS), 128>>>(x);

    const int smemB = 2 * (32 * WS_PITCH * 4) + 2 * 64 * 33 * 4;   // 149,  2*66560+16896
    cudaFuncSetAttribute(lstm_fused_kernel,
                         cudaFuncAttributeMaxDynamicSharedMemorySize, smemB);
    int write_tail = (out_size > T_STEPS * BATCH * HID) ? 1 : 0;
    lstm_fused_kernel<<<NCTA, 256, smemB>>>(Wx, Wh, b, out, write_tail);
}